// round 13
// baseline (speedup 1.0000x reference)
#include <cuda_runtime.h>
#include <cstdint>

// Problem constants
#define VOCAB   100000
#define EMBED   128
#define BATCH   64
#define SEQLEN  2048
#define NTOK    (BATCH * SEQLEN)          // 131072
#define NBLK    148                       // one block per SM -> all co-resident
#define TPB     256
#define RPB     676                       // vocab rows per block (148*676 = 100048)
#define SUB     64                        // rows per subchunk (32 KB)
#define NSUB    11                        // ceil(676/64)
#define BCAP    1024                      // entries per (block,subchunk) bucket
#define TOKPB   886                       // tokens scattered per block (148*886 >= NTOK)
#define RING    3
#define SLOT_BYTES (SUB * 512)            // 32768

// Device scratch (zero-initialized at load; every execution restores the
// all-zero invariant for g_sums / g_done / g_barrier / g_bcount).
__device__ float    g_sums[BATCH * EMBED];
__device__ int      g_done;
__device__ int      g_barrier;
__device__ int      g_bcount[NBLK * NSUB];
__device__ unsigned g_entries[NBLK * NSUB * BCAP];   // stale entries harmless (count gated)

// ---- mbarrier / bulk-async helpers (validated in the passing R9 kernel) ----
__device__ __forceinline__ void mbar_init(uint32_t mbar, uint32_t count) {
    asm volatile("mbarrier.init.shared.b64 [%0], %1;" :: "r"(mbar), "r"(count) : "memory");
}
__device__ __forceinline__ void mbar_expect_tx(uint32_t mbar, uint32_t bytes) {
    asm volatile("mbarrier.arrive.expect_tx.shared.b64 _, [%0], %1;"
                 :: "r"(mbar), "r"(bytes) : "memory");
}
__device__ __forceinline__ void mbar_wait(uint32_t mbar, uint32_t parity) {
    asm volatile(
        "{\n\t"
        ".reg .pred P;\n\t"
        "WAIT_%=:\n\t"
        "mbarrier.try_wait.parity.acquire.cta.shared::cta.b64 P, [%0], %1, 0x989680;\n\t"
        "@P bra.uni DONE_%=;\n\t"
        "bra.uni WAIT_%=;\n\t"
        "DONE_%=:\n\t"
        "}"
        :: "r"(mbar), "r"(parity) : "memory");
}
__device__ __forceinline__ void bulk_g2s(uint32_t smem_dst, const void* gmem_src,
                                         uint32_t bytes, uint32_t mbar) {
    asm volatile(
        "cp.async.bulk.shared::cta.global.mbarrier::complete_tx::bytes "
        "[%0], [%1], %2, [%3];"
        :: "r"(smem_dst), "l"(gmem_src), "r"(bytes), "r"(mbar) : "memory");
}

__device__ __forceinline__ int nvalid_rows(int blk, int s) {
    int start = blk * RPB + s * SUB;
    int nv = VOCAB - start;
    if (nv < 0) nv = 0;
    if (nv > SUB) nv = SUB;
    return nv;
}

// ---------------------------------------------------------------------------
// Persistent kernel, grid = 148 x 256, dynamic smem = RING*32KB (stream ring)
// + 32KB (per-block acc[64][128]).
// ---------------------------------------------------------------------------
__global__ void cbow_stream_kernel(
    const void* __restrict__ xraw,
    const float* __restrict__ emb,
    float* __restrict__ out)
{
    extern __shared__ char dsm[];
    float4* embbuf = (float4*)dsm;                         // [RING][SUB][32] float4
    float*  accf   = (float*)(dsm + RING * SLOT_BYTES);    // [64*128]
    float4* accv   = (float4*)accf;
    __shared__ unsigned long long mbar_s[RING];
    __shared__ int s_is64, s_last;

    const int blk  = blockIdx.x;
    const int tid  = threadIdx.x;
    const int w    = tid >> 5;    // warp 0..7 owns batches [8w, 8w+8)
    const int lane = tid & 31;
    const uint32_t embbase = (uint32_t)__cvta_generic_to_shared(embbuf);

    // ---- init: mbarriers, dtype detect, zero accumulators ----
    if (tid == 0) {
        #pragma unroll
        for (int k = 0; k < RING; k++)
            mbar_init((uint32_t)__cvta_generic_to_shared(&mbar_s[k]), 1);
    }
    if (tid < 32) {
        const long long v = ((const long long*)xraw)[tid];  // first 256B safe both dtypes
        const unsigned bad = __ballot_sync(0xFFFFFFFFu, v < 0 || v >= VOCAB);
        if (tid == 0) s_is64 = (bad == 0u);
    }
    for (int k = tid; k < BATCH * EMBED; k += TPB) accf[k] = 0.0f;
    __syncthreads();
    const int is64 = s_is64;

    // issue subchunk s into ring slot s%RING (caller guarantees nvalid>0;
    // contains a __syncthreads -> must be called uniformly)
    auto issue = [&](int s) {
        const int nv = nvalid_rows(blk, s);
        const int slot = s % RING;
        const uint32_t bar = (uint32_t)__cvta_generic_to_shared(&mbar_s[slot]);
        if (tid == 0) mbar_expect_tx(bar, (uint32_t)nv * 512u);
        __syncthreads();   // expect posted before completions can land
        if (tid < nv) {
            const int v = blk * RPB + s * SUB + tid;
            bulk_g2s(embbase + (uint32_t)(slot * SLOT_BYTES + tid * 512),
                     emb + (size_t)v * EMBED, 512u, bar);
        }
    };

    // ---- prologue: start streaming the table immediately (overlaps scatter) ----
    issue(0); issue(1); issue(2);   // nvalid>0 for s<=2 on every block

    // ---- boundary-correction pre-write: block b (<64) writes out[b][j][:] =
    //      corr_j; the finalizer later adds the full-sequence sum S. ----
    // offsets [-1,-2,+1,+2]:
    //   corr0 = -l0 + e0 ; corr1 = -l0 - l1 + 2e0 ; corr2 = -f0 + e0 ; corr3 = -f0 - f1 + 2e0
    if (blk < BATCH && tid < EMBED) {
        const int b = blk, e = tid;
        long long tf0, tf1, tl0, tl1;
        if (is64) {
            const long long* x64 = (const long long*)xraw;
            tf0 = x64[(size_t)b * SEQLEN + 0];
            tf1 = x64[(size_t)b * SEQLEN + 1];
            tl1 = x64[(size_t)b * SEQLEN + (SEQLEN - 2)];
            tl0 = x64[(size_t)b * SEQLEN + (SEQLEN - 1)];
        } else {
            const int* x32 = (const int*)xraw;
            tf0 = x32[(size_t)b * SEQLEN + 0];
            tf1 = x32[(size_t)b * SEQLEN + 1];
            tl1 = x32[(size_t)b * SEQLEN + (SEQLEN - 2)];
            tl0 = x32[(size_t)b * SEQLEN + (SEQLEN - 1)];
        }
        if (tf0 < 0) tf0 = 0; if (tf0 >= VOCAB) tf0 = VOCAB - 1;
        if (tf1 < 0) tf1 = 0; if (tf1 >= VOCAB) tf1 = VOCAB - 1;
        if (tl0 < 0) tl0 = 0; if (tl0 >= VOCAB) tl0 = VOCAB - 1;
        if (tl1 < 0) tl1 = 0; if (tl1 >= VOCAB) tl1 = VOCAB - 1;

        const float e0 = emb[e];
        const float f0 = emb[(size_t)tf0 * EMBED + e];
        const float f1 = emb[(size_t)tf1 * EMBED + e];
        const float l0 = emb[(size_t)tl0 * EMBED + e];
        const float l1 = emb[(size_t)tl1 * EMBED + e];

        float* o = out + (size_t)b * 4 * EMBED;
        o[0 * EMBED + e] = -l0 + e0;
        o[1 * EMBED + e] = -l0 - l1 + 2.0f * e0;
        o[2 * EMBED + e] = -f0 + e0;
        o[3 * EMBED + e] = -f0 - f1 + 2.0f * e0;
    }

    // ---- Phase A: scatter tokens into per-(owner-block, subchunk) buckets ----
    for (int i = tid; i < TOKPB; i += TPB) {
        const int gi = blk * TOKPB + i;
        if (gi >= NTOK) break;
        long long tv = is64 ? ((const long long*)xraw)[gi]
                            : (long long)((const int*)xraw)[gi];
        if (tv < 0) tv = 0;
        if (tv >= VOCAB) tv = VOCAB - 1;
        const int v  = (int)tv;
        const int b  = gi >> 11;            // gi / SEQLEN
        const int ob = v / RPB;             // owning stream block
        const int loc = v - ob * RPB;
        const int ss = loc >> 6, rr = loc & 63;
        const int bi = ob * NSUB + ss;
        const int j = atomicAdd(&g_bcount[bi], 1);
        if (j < BCAP) g_entries[bi * BCAP + j] = (unsigned)((rr << 6) | b);
    }

    // ---- grid-wide barrier (148 blocks, all resident: 1 block/SM) ----
    __threadfence();
    __syncthreads();
    if (tid == 0) {
        atomicAdd(&g_barrier, 1);
        while (*(volatile int*)&g_barrier < NBLK) __nanosleep(64);
    }
    __syncthreads();
    __threadfence();

    // ---- Phase B: consume streamed subchunks ----
    for (int s = 0; s < NSUB; s++) {
        const int nv = nvalid_rows(blk, s);
        if (nv == 0) break;                       // only possible at the tail
        const int slot = s % RING;
        mbar_wait((uint32_t)__cvta_generic_to_shared(&mbar_s[slot]),
                  (uint32_t)((s / RING) & 1));

        const int bi  = blk * NSUB + s;
        int cnt = g_bcount[bi];
        if (cnt > BCAP) cnt = BCAP;
        const unsigned* ep = &g_entries[bi * BCAP];
        const float4* ebuf = embbuf + slot * (SLOT_BYTES / 16);

        for (int i = 0; i < cnt; i++) {
            const unsigned e = __ldg(ep + i);     // warp-uniform broadcast
            const int b = (int)(e & 63u);
            if ((b >> 3) != w) continue;          // warp w owns batches 8w..8w+7
            const int r = (int)(e >> 6);
            const float4 val = ebuf[r * 32 + lane];
            float4* a = &accv[b * 32 + lane];     // exclusive to this warp: no races
            a->x += val.x; a->y += val.y; a->z += val.z; a->w += val.w;
        }
        __syncthreads();                          // slot + entries fully consumed
        if (tid == 0) g_bcount[bi] = 0;           // restore zero-invariant
        const int nxt = s + RING;
        if (nxt < NSUB && nvalid_rows(blk, nxt) > 0) issue(nxt);  // uniform call
    }

    // ---- per-block reduce into the global per-batch sums ----
    for (int k = tid; k < BATCH * EMBED; k += TPB)
        atomicAdd(&g_sums[k], accf[k]);

    __threadfence();
    __syncthreads();
    if (tid == 0) {
        const int old = atomicAdd(&g_done, 1);
        s_last = (old == NBLK - 1);
    }
    __syncthreads();

    // ---- finalize: last block adds S to the pre-written corrections ----
    if (s_last) {
        for (int k = tid; k < BATCH * EMBED; k += TPB) {
            const float S = *(volatile float*)&g_sums[k];
            const int b = k >> 7, e = k & 127;
            float* o = out + (size_t)b * 4 * EMBED + e;
            o[0 * EMBED] += S;
            o[1 * EMBED] += S;
            o[2 * EMBED] += S;
            o[3 * EMBED] += S;
            g_sums[k] = 0.0f;                     // restore zero-invariant
        }
        __syncthreads();
        if (tid == 0) { g_done = 0; g_barrier = 0; }
    }
}

// ---------------------------------------------------------------------------
// Launch. Input order resolved from element counts:
//   x   : BATCH*SEQLEN = 131072 elements
//   emb : VOCAB*EMBED  = 12800000 elements
// ---------------------------------------------------------------------------
extern "C" void kernel_launch(void* const* d_in, const int* in_sizes, int n_in,
                              void* d_out, int out_size) {
    int ix = 0, ie = 1;
    if (in_sizes[0] != BATCH * SEQLEN) { ix = 1; ie = 0; }

    const void*  x   = d_in[ix];
    const float* emb = (const float*)d_in[ie];
    float*       out = (float*)d_out;

    const int smem = RING * SLOT_BYTES + BATCH * EMBED * (int)sizeof(float); // 131072
    static int attr_set = 0;
    if (!attr_set) {
        cudaFuncSetAttribute(cbow_stream_kernel,
                             cudaFuncAttributeMaxDynamicSharedMemorySize, smem);
        attr_set = 1;
    }

    cbow_stream_kernel<<<NBLK, TPB, smem>>>(x, emb, out);
}

// round 14
// speedup vs baseline: 2.5152x; 2.5152x over previous
#include <cuda_runtime.h>
#include <cstdint>

// Problem constants
#define VOCAB   100000
#define EMBED   128
#define BATCH   64
#define SEQLEN  2048
#define NTOK    (BATCH * SEQLEN)          // 131072
#define NBLK    148                       // one block per SM -> co-resident
#define TPB     256                       // 8 warps
#define RPB     676                       // vocab rows per block (148*676 >= 100000)
#define SUB     64                        // rows per subchunk = 32 KB contiguous
#define NSUB    11                        // ceil(676/64)
#define NGRP    8                         // batch groups (warp w owns batches 8w..8w+7)
#define BCAP    128                       // entries per bucket (mean ~10.5, Poisson tail safe)
#define TOKPB   886                       // tokens scattered per block (148*886 >= NTOK)
#define RING    4
#define SLOT_BYTES (SUB * 512)            // 32768

// Device scratch (zero-initialized at load; every execution restores the
// all-zero invariant for g_sums / g_done / g_barrier / g_bcount).
__device__ float    g_sums[BATCH * EMBED];
__device__ int      g_done;
__device__ int      g_barrier;
__device__ int      g_bcount[NBLK * NSUB * NGRP];
__device__ unsigned g_entries[NBLK * NSUB * NGRP * BCAP];  // stale data harmless (count-gated)

// ---- mbarrier / bulk-async helpers ----
__device__ __forceinline__ void mbar_init(uint32_t mbar, uint32_t count) {
    asm volatile("mbarrier.init.shared.b64 [%0], %1;" :: "r"(mbar), "r"(count) : "memory");
}
__device__ __forceinline__ void mbar_expect_tx(uint32_t mbar, uint32_t bytes) {
    asm volatile("mbarrier.arrive.expect_tx.shared.b64 _, [%0], %1;"
                 :: "r"(mbar), "r"(bytes) : "memory");
}
__device__ __forceinline__ void mbar_wait(uint32_t mbar, uint32_t parity) {
    asm volatile(
        "{\n\t"
        ".reg .pred P;\n\t"
        "WAIT_%=:\n\t"
        "mbarrier.try_wait.parity.acquire.cta.shared::cta.b64 P, [%0], %1, 0x989680;\n\t"
        "@P bra.uni DONE_%=;\n\t"
        "bra.uni WAIT_%=;\n\t"
        "DONE_%=:\n\t"
        "}"
        :: "r"(mbar), "r"(parity) : "memory");
}
__device__ __forceinline__ void bulk_g2s(uint32_t smem_dst, const void* gmem_src,
                                         uint32_t bytes, uint32_t mbar) {
    asm volatile(
        "cp.async.bulk.shared::cta.global.mbarrier::complete_tx::bytes "
        "[%0], [%1], %2, [%3];"
        :: "r"(smem_dst), "l"(gmem_src), "r"(bytes), "r"(mbar) : "memory");
}
__device__ __forceinline__ void red_add_f32(float* p, float v) {
    asm volatile("red.global.add.f32 [%0], %1;" :: "l"(p), "f"(v) : "memory");
}

__device__ __forceinline__ int nvalid_rows(int blk, int s) {
    int start = blk * RPB + s * SUB;
    int nv = VOCAB - start;
    if (nv < 0) nv = 0;
    if (nv > SUB) nv = SUB;
    return nv;
}

// ---------------------------------------------------------------------------
// Persistent kernel, grid = 148 x 256.
// dyn smem: RING*32KB stream ring + 32KB acc[64][128] = 160KB.
// ---------------------------------------------------------------------------
__global__ void cbow_stream_kernel(
    const void* __restrict__ xraw,
    const float* __restrict__ emb,
    float* __restrict__ out)
{
    extern __shared__ char dsm[];
    float4* embbuf = (float4*)dsm;                         // [RING][SUB][32] float4
    float*  accf   = (float*)(dsm + RING * SLOT_BYTES);    // [64*128]
    float4* accv   = (float4*)accf;
    __shared__ unsigned long long mbar_s[RING];
    __shared__ int s_is64, s_last;

    const int blk  = blockIdx.x;
    const int tid  = threadIdx.x;
    const int w    = tid >> 5;    // warp id = batch group
    const int lane = tid & 31;
    const uint32_t embbase = (uint32_t)__cvta_generic_to_shared(embbuf);

    // ---- init ----
    if (tid == 0) {
        #pragma unroll
        for (int k = 0; k < RING; k++)
            mbar_init((uint32_t)__cvta_generic_to_shared(&mbar_s[k]), 1);
    }
    if (tid < 32) {
        const long long v = ((const long long*)xraw)[tid];  // first 256B safe both dtypes
        const unsigned bad = __ballot_sync(0xFFFFFFFFu, v < 0 || v >= VOCAB);
        if (tid == 0) s_is64 = (bad == 0u);
    }
    for (int k = tid; k < BATCH * EMBED; k += TPB) accf[k] = 0.0f;
    __syncthreads();
    const int is64 = s_is64;

    // Issue subchunk s as ONE contiguous 32KB (nv*512B) bulk into slot s%RING.
    // Contains __syncthreads -> must be called uniformly; caller ensures nv>0.
    auto issue = [&](int s) {
        const int nv = nvalid_rows(blk, s);
        const int slot = s & (RING - 1);
        const uint32_t bar = (uint32_t)__cvta_generic_to_shared(&mbar_s[slot]);
        if (tid == 0) mbar_expect_tx(bar, (uint32_t)nv * 512u);
        __syncthreads();   // expect posted before completion can land
        if (tid == 0) {
            const int vrow = blk * RPB + s * SUB;
            bulk_g2s(embbase + (uint32_t)slot * SLOT_BYTES,
                     emb + (size_t)vrow * EMBED, (uint32_t)nv * 512u, bar);
        }
    };

    // ---- prologue: start the sequential table sweep immediately ----
    issue(0); issue(1); issue(2); issue(3);   // nv>0 for s<=3 on every block

    // ---- boundary-correction pre-write (block b < 64): out[b][j] = corr_j;
    //      finalizer adds the full-sequence sum S afterwards.
    // offsets [-1,-2,+1,+2]:
    //   corr0=-l0+e0; corr1=-l0-l1+2e0; corr2=-f0+e0; corr3=-f0-f1+2e0
    if (blk < BATCH && tid < EMBED) {
        const int b = blk, e = tid;
        long long tf0, tf1, tl0, tl1;
        if (is64) {
            const long long* x64 = (const long long*)xraw;
            tf0 = x64[(size_t)b * SEQLEN + 0];
            tf1 = x64[(size_t)b * SEQLEN + 1];
            tl1 = x64[(size_t)b * SEQLEN + (SEQLEN - 2)];
            tl0 = x64[(size_t)b * SEQLEN + (SEQLEN - 1)];
        } else {
            const int* x32 = (const int*)xraw;
            tf0 = x32[(size_t)b * SEQLEN + 0];
            tf1 = x32[(size_t)b * SEQLEN + 1];
            tl1 = x32[(size_t)b * SEQLEN + (SEQLEN - 2)];
            tl0 = x32[(size_t)b * SEQLEN + (SEQLEN - 1)];
        }
        if (tf0 < 0) tf0 = 0; if (tf0 >= VOCAB) tf0 = VOCAB - 1;
        if (tf1 < 0) tf1 = 0; if (tf1 >= VOCAB) tf1 = VOCAB - 1;
        if (tl0 < 0) tl0 = 0; if (tl0 >= VOCAB) tl0 = VOCAB - 1;
        if (tl1 < 0) tl1 = 0; if (tl1 >= VOCAB) tl1 = VOCAB - 1;

        const float e0 = emb[e];
        const float f0 = emb[(size_t)tf0 * EMBED + e];
        const float f1 = emb[(size_t)tf1 * EMBED + e];
        const float l0 = emb[(size_t)tl0 * EMBED + e];
        const float l1 = emb[(size_t)tl1 * EMBED + e];

        float* o = out + (size_t)b * 4 * EMBED;
        o[0 * EMBED + e] = -l0 + e0;
        o[1 * EMBED + e] = -l0 - l1 + 2.0f * e0;
        o[2 * EMBED + e] = -f0 + e0;
        o[3 * EMBED + e] = -f0 - f1 + 2.0f * e0;
    }

    // ---- Phase A: scatter tokens into (owner block, subchunk, batch-group)
    //      buckets. Entry = (row-in-subchunk << 6) | batch.
    for (int i = tid; i < TOKPB; i += TPB) {
        const int gi = blk * TOKPB + i;
        if (gi >= NTOK) break;
        long long tv = is64 ? ((const long long*)xraw)[gi]
                            : (long long)((const int*)xraw)[gi];
        if (tv < 0) tv = 0;
        if (tv >= VOCAB) tv = VOCAB - 1;
        const int v   = (int)tv;
        const int b   = gi >> 11;            // gi / SEQLEN
        const int ob  = v / RPB;             // owning stream block
        const int loc = v - ob * RPB;
        const int bi  = ((ob * NSUB + (loc >> 6)) << 3) + (b >> 3);
        const int j = atomicAdd(&g_bcount[bi], 1);
        if (j < BCAP) g_entries[bi * BCAP + j] = (unsigned)(((loc & 63) << 6) | b);
    }

    // ---- grid-wide barrier (148 co-resident blocks) ----
    __threadfence();
    __syncthreads();
    if (tid == 0) {
        atomicAdd(&g_barrier, 1);
        while (*(volatile int*)&g_barrier < NBLK) __nanosleep(64);
    }
    __syncthreads();
    __threadfence();

    // ---- Phase B: consume streamed subchunks; warp w reads ONLY its bucket ----
    for (int s = 0; s < NSUB; s++) {
        const int nv = nvalid_rows(blk, s);
        if (nv == 0) break;                   // tail only (block-uniform)
        const int slot = s & (RING - 1);
        mbar_wait((uint32_t)__cvta_generic_to_shared(&mbar_s[slot]),
                  (uint32_t)((s >> 2) & 1));

        const int bi  = ((blk * NSUB + s) << 3) + w;
        int cnt = g_bcount[bi];
        if (cnt > BCAP) cnt = BCAP;
        const unsigned* ep = &g_entries[bi * BCAP];
        const float4* ebuf = embbuf + slot * (SLOT_BYTES / 16);

        for (int i = 0; i < cnt; i++) {
            const unsigned e = __ldg(ep + i);          // warp-uniform
            const int b = (int)(e & 63u);              // in [8w, 8w+8): ours
            const int r = (int)(e >> 6);
            const float4 val = ebuf[r * 32 + lane];
            float4* a = &accv[b * 32 + lane];          // warp-exclusive rows
            a->x += val.x; a->y += val.y; a->z += val.z; a->w += val.w;
        }
        __syncthreads();                               // slot fully consumed
        if (tid < NGRP) g_bcount[((blk * NSUB + s) << 3) + tid] = 0;  // zero-invariant
        const int nxt = s + RING;
        if (nxt < NSUB && nvalid_rows(blk, nxt) > 0) issue(nxt);      // uniform
    }

    // ---- epilogue: reduce block accumulator into global per-batch sums ----
    for (int k = tid; k < BATCH * EMBED; k += TPB)
        red_add_f32(&g_sums[k], accf[k]);

    __threadfence();
    __syncthreads();
    if (tid == 0) {
        const int old = atomicAdd(&g_done, 1);
        s_last = (old == NBLK - 1);
    }
    __syncthreads();

    // ---- finalize: last block adds S to the pre-written corrections ----
    if (s_last) {
        for (int k = tid; k < BATCH * EMBED; k += TPB) {
            const float S = *(volatile float*)&g_sums[k];
            const int b = k >> 7, e = k & 127;
            float* o = out + (size_t)b * 4 * EMBED + e;
            #pragma unroll
            for (int j = 0; j < 4; j++) {
                const float cur = *(volatile float*)&o[j * EMBED];
                o[j * EMBED] = cur + S;
            }
            g_sums[k] = 0.0f;                          // zero-invariant
        }
        __syncthreads();
        if (tid == 0) { g_done = 0; g_barrier = 0; }
    }
}

// ---------------------------------------------------------------------------
// Launch. Input order resolved from element counts:
//   x   : BATCH*SEQLEN = 131072 elements
//   emb : VOCAB*EMBED  = 12800000 elements
// ---------------------------------------------------------------------------
extern "C" void kernel_launch(void* const* d_in, const int* in_sizes, int n_in,
                              void* d_out, int out_size) {
    int ix = 0, ie = 1;
    if (in_sizes[0] != BATCH * SEQLEN) { ix = 1; ie = 0; }

    const void*  x   = d_in[ix];
    const float* emb = (const float*)d_in[ie];
    float*       out = (float*)d_out;

    const int smem = RING * SLOT_BYTES + BATCH * EMBED * (int)sizeof(float); // 163840
    static int attr_set = 0;
    if (!attr_set) {
        cudaFuncSetAttribute(cbow_stream_kernel,
                             cudaFuncAttributeMaxDynamicSharedMemorySize, smem);
        attr_set = 1;
    }

    cbow_stream_kernel<<<NBLK, TPB, smem>>>(x, emb, out);
}

// round 16
// speedup vs baseline: 8.1364x; 3.2348x over previous
#include <cuda_runtime.h>
#include <cuda_bf16.h>
#include <cstdint>

// Problem constants
#define VOCAB   100000
#define EMBED   128
#define BATCH   64
#define SEQLEN  2048
#define NCHUNK  16
#define CHUNK   (SEQLEN / NCHUNK)   // 128 tokens per block

// Device scratch (zero-initialized at load; every execution restores the
// all-zero invariant, so graph replays are deterministic).
__device__ float g_sums[BATCH * EMBED];
__device__ int   g_count[BATCH];

// ---------------------------------------------------------------------------
// Single fused kernel. grid = (NCHUNK, BATCH) = (16, 64) = 1024 blocks x 128
// (6.9 blocks/SM, single wave under the 8-block register cap).
//
// Best-of-session configuration (12.51us):
//  1. prefetch.global.L2 issued for ALL 32 of a thread's row-chunks before
//     any LDG: prefetches cost no registers and no scoreboard slot, so each
//     warp immediately posts its full request set; the later LDGs merge with
//     the in-flight prefetches instead of starting cold.
//  2. Explicit 8-deep load batches + __launch_bounds__(128, 8) (~64 regs)
//     keep ~8 LDG.128 in flight per warp, with two accumulators to split
//     the FADD dependency chain.
//  No inter-block waits anywhere: every block runs to completion
//  independently; the finalize trigger is a monotonic atomic counter.
// ---------------------------------------------------------------------------
__global__ __launch_bounds__(128, 8) void cbow_fused_kernel(
    const void* __restrict__ xraw,     // [BATCH, SEQLEN] token ids (int64 or int32)
    const float* __restrict__ emb,     // [VOCAB, EMBED] f32
    float* __restrict__ out)           // [BATCH, 4, EMBED] f32
{
    __shared__ int    toks[CHUNK];
    __shared__ float4 part[128];
    __shared__ int    s_is64;
    __shared__ int    s_last;

    const int b    = blockIdx.y;
    const int base = blockIdx.x * CHUNK;
    const int tid  = threadIdx.x;

    // ---- Phase 0: dtype detection (warp 0; first 256B safe under both) ----
    if (tid < 32) {
        const long long v = ((const long long*)xraw)[tid];
        const unsigned bad = __ballot_sync(0xFFFFFFFFu, v < 0 || v >= VOCAB);
        if (tid == 0) s_is64 = (bad == 0u);
    }
    __syncthreads();
    const int is64 = s_is64;

    // ---- Phase 1: stage this chunk's 128 token ids (clamped int32) ----
    {
        const int idx = b * SEQLEN + base + tid;
        long long v = is64 ? ((const long long*)xraw)[idx]
                           : (long long)((const int*)xraw)[idx];
        if (v < 0) v = 0;
        if (v >= VOCAB) v = VOCAB - 1;
        toks[tid] = (int)v;
    }
    __syncthreads();

    // ---- Phase 2: prefetch-decoupled, deep-batched gather-accumulate ----
    const int c   = tid & 31;   // float4 column within the 128-float row
    const int gph = tid >> 5;   // token phase (0..3); this thread's rows are
                                // t = gph, gph+4, ..., gph+124  (32 rows)

    // 2a: post all 32 requests to L2 up-front (no regs, no scoreboard).
    #pragma unroll
    for (int t = gph; t < CHUNK; t += 4) {
        const float4* p =
            reinterpret_cast<const float4*>(emb + (size_t)toks[t] * EMBED) + c;
        asm volatile("prefetch.global.L2 [%0];" :: "l"(p));
    }

    // 2b: 4 rounds of 8 explicitly-batched loads (8 LDG.128 in flight/warp).
    float4 acc0 = make_float4(0.f, 0.f, 0.f, 0.f);
    float4 acc1 = make_float4(0.f, 0.f, 0.f, 0.f);
    #pragma unroll
    for (int round = 0; round < 4; round++) {
        float4 v[8];
        #pragma unroll
        for (int j = 0; j < 8; j++) {
            const int t = gph + (round * 8 + j) * 4;
            v[j] = __ldg(
                reinterpret_cast<const float4*>(emb + (size_t)toks[t] * EMBED) + c);
        }
        #pragma unroll
        for (int j = 0; j < 8; j += 2) {
            acc0.x += v[j].x;     acc0.y += v[j].y;
            acc0.z += v[j].z;     acc0.w += v[j].w;
            acc1.x += v[j + 1].x; acc1.y += v[j + 1].y;
            acc1.z += v[j + 1].z; acc1.w += v[j + 1].w;
        }
    }
    part[tid] = make_float4(acc0.x + acc1.x, acc0.y + acc1.y,
                            acc0.z + acc1.z, acc0.w + acc1.w);
    __syncthreads();

    // ---- Phase 3: reduce the 4 token phases, atomic into per-batch sum ----
    if (gph == 0) {
        const float4 p0 = part[c];
        const float4 p1 = part[32 + c];
        const float4 p2 = part[64 + c];
        const float4 p3 = part[96 + c];
        float* dst = &g_sums[b * EMBED + c * 4];
        atomicAdd(dst + 0, p0.x + p1.x + p2.x + p3.x);
        atomicAdd(dst + 1, p0.y + p1.y + p2.y + p3.y);
        atomicAdd(dst + 2, p0.z + p1.z + p2.z + p3.z);
        atomicAdd(dst + 3, p0.w + p1.w + p2.w + p3.w);
    }

    // Make our atomics visible device-wide before signalling completion.
    __threadfence();
    __syncthreads();
    if (tid == 0) {
        const int old = atomicAdd(&g_count[b], 1);
        s_last = (old == NCHUNK - 1);
    }
    __syncthreads();

    // ---- Phase 4: last block of this batch finalizes ----
    // Output [B, 4, E], offsets [-1, -2, +1, +2]:
    //   off -1: S - emb[x[L-1]]               + 1*emb[0]
    //   off -2: S - emb[x[L-1]] - emb[x[L-2]] + 2*emb[0]
    //   off +1: S - emb[x[0]]                 + 1*emb[0]
    //   off +2: S - emb[x[0]]   - emb[x[1]]   + 2*emb[0]
    if (s_last) {
        const int e = tid;

        // Volatile read: atomics land in L2; bypass any stale L1 line.
        const float S = *(volatile float*)&g_sums[b * EMBED + e];

        long long tf0, tf1, tl0, tl1;
        if (is64) {
            const long long* x64 = (const long long*)xraw;
            tf0 = x64[(size_t)b * SEQLEN + 0];
            tf1 = x64[(size_t)b * SEQLEN + 1];
            tl1 = x64[(size_t)b * SEQLEN + (SEQLEN - 2)];
            tl0 = x64[(size_t)b * SEQLEN + (SEQLEN - 1)];
        } else {
            const int* x32 = (const int*)xraw;
            tf0 = x32[(size_t)b * SEQLEN + 0];
            tf1 = x32[(size_t)b * SEQLEN + 1];
            tl1 = x32[(size_t)b * SEQLEN + (SEQLEN - 2)];
            tl0 = x32[(size_t)b * SEQLEN + (SEQLEN - 1)];
        }
        if (tf0 < 0) tf0 = 0; if (tf0 >= VOCAB) tf0 = VOCAB - 1;
        if (tf1 < 0) tf1 = 0; if (tf1 >= VOCAB) tf1 = VOCAB - 1;
        if (tl0 < 0) tl0 = 0; if (tl0 >= VOCAB) tl0 = VOCAB - 1;
        if (tl1 < 0) tl1 = 0; if (tl1 >= VOCAB) tl1 = VOCAB - 1;

        const float e0 = emb[e];  // emb[token 0][e]
        const float f0 = emb[(size_t)tf0 * EMBED + e];
        const float f1 = emb[(size_t)tf1 * EMBED + e];
        const float l0 = emb[(size_t)tl0 * EMBED + e];
        const float l1 = emb[(size_t)tl1 * EMBED + e];

        float* o = out + (size_t)b * 4 * EMBED;
        o[0 * EMBED + e] = S - l0 + e0;                  // offset -1
        o[1 * EMBED + e] = S - l0 - l1 + 2.0f * e0;      // offset -2
        o[2 * EMBED + e] = S - f0 + e0;                  // offset +1
        o[3 * EMBED + e] = S - f0 - f1 + 2.0f * e0;      // offset +2

        // Restore the zero-invariant for the next graph replay.
        g_sums[b * EMBED + e] = 0.0f;
        if (tid == 0) g_count[b] = 0;
    }
}

// ---------------------------------------------------------------------------
// Launch. Input order resolved from element counts:
//   x   : BATCH*SEQLEN = 131072 elements
//   emb : VOCAB*EMBED  = 12800000 elements
// ---------------------------------------------------------------------------
extern "C" void kernel_launch(void* const* d_in, const int* in_sizes, int n_in,
                              void* d_out, int out_size) {
    int ix = 0, ie = 1;
    if (in_sizes[0] != BATCH * SEQLEN) { ix = 1; ie = 0; }

    const void*  x   = d_in[ix];
    const float* emb = (const float*)d_in[ie];
    float*       out = (float*)d_out;

    dim3 grid(NCHUNK, BATCH);
    cbow_fused_kernel<<<grid, 128>>>(x, emb, out);
}